// round 2
// baseline (speedup 1.0000x reference)
#include <cuda_runtime.h>
#include <cuda_bf16.h>

#define NN 2048
#define HH 16
#define FIN 128

// Output layout (float32): node_out [2048*2], edge_out [2048*2048], start [2048*2048], end [2048*2048]
#define OFF_NODE  0
#define OFF_EDGE  4096
#define OFF_START (4096 + 4194304)
#define OFF_END   (4096 + 4194304 + 4194304)

// Scratch (static __device__ — no allocation)
__device__ float g_xw1[NN * HH];
__device__ float g_deg[NN];
__device__ float g_dinv[NN];
__device__ float g_agg1[NN * HH];
__device__ float g_h[NN * HH];
__device__ float g_xw2[NN * 2];
__device__ float g_agg2[NN * 2];
__device__ float g_A[NN * HH];
__device__ float g_Bb[NN * HH];
__device__ int   g_i64;

// ---------------------------------------------------------------------------
// Detect whether edge_index buffer is int64 or int32. Values are in [0,2048),
// so for int64 every odd 32-bit word is 0; for int32 random values that's
// essentially impossible across 8 samples.
__global__ void k_detect(const void* ei) {
    const unsigned int* w = (const unsigned int*)ei;
    unsigned int acc = 0;
#pragma unroll
    for (int i = 1; i < 16; i += 2) acc |= w[i];
    g_i64 = (acc == 0u) ? 1 : 0;
}

__device__ __forceinline__ void load_edge(const void* ei, int e, int E, int& s, int& d) {
    if (g_i64) {
        const long long* p = (const long long*)ei;
        s = (int)p[e];
        d = (int)p[E + e];
    } else {
        const int* p = (const int*)ei;
        s = p[e];
        d = p[E + e];
    }
}

// ---------------------------------------------------------------------------
__global__ void k_init() {
    int t = blockIdx.x * blockDim.x + threadIdx.x;
    if (t < NN * HH) g_agg1[t] = 0.0f;
    if (t < NN * 2)  g_agg2[t] = 0.0f;
    if (t < NN)      g_deg[t]  = 1.0f;  // self-loop
}

// xw1 = x @ W1   [2048,128]@[128,16]
__global__ void k_xw1(const float* __restrict__ x, const float* __restrict__ W1) {
    __shared__ float sW[FIN * HH];
    int t = threadIdx.x;
    for (int idx = t; idx < FIN * HH; idx += 256) sW[idx] = W1[idx];
    __syncthreads();
    int o = blockIdx.x * 256 + t;
    int row = o >> 4, col = o & 15;
    const float* xr = x + row * FIN;
    float acc = 0.0f;
#pragma unroll 8
    for (int k = 0; k < FIN; k++) acc = fmaf(xr[k], sW[k * HH + col], acc);
    g_xw1[o] = acc;
}

__global__ void k_deg(const void* ei, int E) {
    int e = blockIdx.x * blockDim.x + threadIdx.x;
    if (e >= E) return;
    int s, d;
    load_edge(ei, e, E, s, d);
    atomicAdd(&g_deg[d], 1.0f);
}

__global__ void k_dinv() {
    int i = blockIdx.x * blockDim.x + threadIdx.x;
    if (i < NN) g_dinv[i] = rsqrtf(g_deg[i]);
}

__global__ void k_agg1(const void* ei, int E) {
    int e = blockIdx.x * blockDim.x + threadIdx.x;
    if (e >= E) return;
    int s, d;
    load_edge(ei, e, E, s, d);
    float nm = g_dinv[s] * g_dinv[d];
    const float* xs = g_xw1 + s * HH;
    float* ad = g_agg1 + d * HH;
#pragma unroll
    for (int c = 0; c < HH; c++) atomicAdd(&ad[c], xs[c] * nm);
}

// h = relu(agg1 + self + b1); xw2 = h@W2; A = h@Wc1[:16]; Bb = h@Wc1[16:] + bc1
__global__ void k_h(const float* __restrict__ b1, const float* __restrict__ W2,
                    const float* __restrict__ Wc1, const float* __restrict__ bc1) {
    __shared__ float sWc1[32 * HH];
    __shared__ float sW2[HH * 2];
    int t = threadIdx.x;
    for (int idx = t; idx < 32 * HH; idx += blockDim.x) sWc1[idx] = Wc1[idx];
    if (t < HH * 2) sW2[t] = W2[t];
    __syncthreads();
    int i = blockIdx.x * blockDim.x + t;
    if (i >= NN) return;
    float di = g_dinv[i];
    float ds = di * di;
    float hv[HH];
#pragma unroll
    for (int c = 0; c < HH; c++) {
        float v = g_agg1[i * HH + c] + g_xw1[i * HH + c] * ds + b1[c];
        hv[c] = fmaxf(v, 0.0f);
        g_h[i * HH + c] = hv[c];
    }
#pragma unroll
    for (int o = 0; o < 2; o++) {
        float a = 0.0f;
#pragma unroll
        for (int c = 0; c < HH; c++) a = fmaf(hv[c], sW2[c * 2 + o], a);
        g_xw2[i * 2 + o] = a;
    }
#pragma unroll
    for (int o = 0; o < HH; o++) {
        float a = 0.0f, b = bc1[o];
#pragma unroll
        for (int c = 0; c < HH; c++) {
            a = fmaf(hv[c], sWc1[c * HH + o], a);
            b = fmaf(hv[c], sWc1[(HH + c) * HH + o], b);
        }
        g_A[i * HH + o] = a;
        g_Bb[i * HH + o] = b;
    }
}

__global__ void k_agg2(const void* ei, int E) {
    int e = blockIdx.x * blockDim.x + threadIdx.x;
    if (e >= E) return;
    int s, d;
    load_edge(ei, e, E, s, d);
    float nm = g_dinv[s] * g_dinv[d];
    atomicAdd(&g_agg2[d * 2 + 0], g_xw2[s * 2 + 0] * nm);
    atomicAdd(&g_agg2[d * 2 + 1], g_xw2[s * 2 + 1] * nm);
}

__global__ void k_node(const float* __restrict__ b2, float* __restrict__ out) {
    int i = blockIdx.x * blockDim.x + threadIdx.x;
    if (i >= NN) return;
    float di = g_dinv[i];
    float ds = di * di;
    out[OFF_NODE + i * 2 + 0] = g_agg2[i * 2 + 0] + g_xw2[i * 2 + 0] * ds + b2[0];
    out[OFF_NODE + i * 2 + 1] = g_agg2[i * 2 + 1] + g_xw2[i * 2 + 1] * ds + b2[1];
}

// edge_out[i*2048+j] = sigmoid( sum_c relu(A[i][c]+Bb[j][c]) * Wc2[c] + bc2 )
// Thread per j (coalesced stores), i-loop with A tile in smem (broadcast reads).
__global__ void __launch_bounds__(256) k_edge(const float* __restrict__ Wc2,
                                              const float* __restrict__ bc2,
                                              float* __restrict__ out) {
    __shared__ float sA[128 * HH];
    int t = threadIdx.x;
    int j = blockIdx.x * 256 + t;
    int i0 = blockIdx.y * 128;
    for (int idx = t; idx < 128 * HH; idx += 256) sA[idx] = g_A[i0 * HH + idx];
    float w[HH];
#pragma unroll
    for (int c = 0; c < HH; c++) w[c] = Wc2[c];
    float bb = bc2[0];
    float Bv[HH];
#pragma unroll
    for (int c = 0; c < HH; c++) Bv[c] = g_Bb[j * HH + c];
    __syncthreads();
    float* op = out + OFF_EDGE + i0 * NN + j;
#pragma unroll 4
    for (int ii = 0; ii < 128; ii++) {
        float acc = bb;
#pragma unroll
        for (int c = 0; c < HH; c++) {
            float tt = sA[ii * HH + c] + Bv[c];
            acc = fmaf(fmaxf(tt, 0.0f), w[c], acc);
        }
        float p = __expf(-acc);
        op[ii * NN] = __fdividef(1.0f, 1.0f + p);
    }
}

// full_edge_index: start[k]=k/2048, end[k]=k%2048, written as float4 pairs
__global__ void k_index(float* __restrict__ out) {
    int t = blockIdx.x * blockDim.x + threadIdx.x;  // 1,048,576 threads
    int k = t * 4;
    float fi = (float)(k >> 11);
    int j = k & 2047;
    float4 s4 = make_float4(fi, fi, fi, fi);
    float4 e4 = make_float4((float)j, (float)(j + 1), (float)(j + 2), (float)(j + 3));
    ((float4*)(out + OFF_START))[t] = s4;
    ((float4*)(out + OFF_END))[t] = e4;
}

// ---------------------------------------------------------------------------
extern "C" void kernel_launch(void* const* d_in, const int* in_sizes, int n_in,
                              void* d_out, int out_size) {
    const float* x   = (const float*)d_in[0];
    const void*  ei  = d_in[1];
    const float* W1  = (const float*)d_in[2];
    const float* b1  = (const float*)d_in[3];
    const float* W2  = (const float*)d_in[4];
    const float* b2  = (const float*)d_in[5];
    const float* Wc1 = (const float*)d_in[6];
    const float* bc1 = (const float*)d_in[7];
    const float* Wc2 = (const float*)d_in[8];
    const float* bc2 = (const float*)d_in[9];
    float* out = (float*)d_out;

    int E = in_sizes[1] / 2;

    k_detect<<<1, 1>>>(ei);
    k_init<<<(NN * HH + 255) / 256, 256>>>();
    k_xw1<<<(NN * HH) / 256, 256>>>(x, W1);
    k_deg<<<(E + 255) / 256, 256>>>(ei, E);
    k_dinv<<<(NN + 255) / 256, 256>>>();
    k_agg1<<<(E + 255) / 256, 256>>>(ei, E);
    k_h<<<(NN + 255) / 256, 256>>>(b1, W2, Wc1, bc1);
    k_agg2<<<(E + 255) / 256, 256>>>(ei, E);
    k_node<<<(NN + 255) / 256, 256>>>(b2, out);
    dim3 eg(NN / 256, NN / 128);
    k_edge<<<eg, 256>>>(Wc2, bc2, out);
    k_index<<<(NN * NN / 4) / 256, 256>>>(out);
}

// round 4
// speedup vs baseline: 1.2753x; 1.2753x over previous
#include <cuda_runtime.h>
#include <cuda_bf16.h>

#define NN 2048
#define HH 16
#define FIN 128

// Output layout (float32): node_out [2048*2], edge_out [2048^2], start [2048^2], end [2048^2]
#define OFF_NODE  0
#define OFF_EDGE  4096
#define OFF_START (4096 + 4194304)
#define OFF_END   (4096 + 4194304 + 4194304)

// Scratch (static __device__ globals: zero-initialized at load; every kernel_launch
// call leaves them re-zeroed for the next call, so graph replays are deterministic).
__device__ float g_xw1[NN * HH];
__device__ float g_deg[NN];    // reset to 0 by k_dinv
__device__ float g_dinv[NN];
__device__ float g_agg1[NN * HH];  // reset to 0 by k_h
__device__ float g_xw2[NN * 2];
__device__ float g_agg2[NN * 2];   // reset to 0 by k_node
__device__ float g_A[NN * HH];
__device__ float g_Bb[NN * HH];

// ---------------------------------------------------------------------------
// Inline dtype sniff: edge values < 2048, so for int64 the odd 32-bit words of
// the first 4 edges are all zero. For int32 that needs 4 random values in
// [0,2048) to all be 0: p ~ 6e-14. Two uint4 loads, L1-broadcast, ~free.
__device__ __forceinline__ bool is_i64(const void* ei) {
    const uint4* p = (const uint4*)ei;
    uint4 a = __ldg(p), b = __ldg(p + 1);
    return ((a.y | a.w | b.y | b.w) == 0u);
}

__device__ __forceinline__ int edge_at(const void* ei, bool i64, long long idx) {
    if (i64) return (int)__ldg((const long long*)ei + idx);
    return __ldg((const int*)ei + idx);
}

// ---------------------------------------------------------------------------
// Fused: blocks [0,128) compute xw1 = x@W1; blocks [128, 128+E/1024) count degrees
// (4 edges/thread, vectorized loads).
__global__ void k_pre(const float* __restrict__ x, const float* __restrict__ W1,
                      const void* __restrict__ ei, int E) {
    if (blockIdx.x < 128) {
        __shared__ float sW[FIN * HH];
        int t = threadIdx.x;
        for (int idx = t; idx < FIN * HH; idx += 256) sW[idx] = W1[idx];
        __syncthreads();
        int o = blockIdx.x * 256 + t;
        int row = o >> 4, col = o & 15;
        const float* xr = x + row * FIN;
        float acc = 0.0f;
#pragma unroll 8
        for (int k = 0; k < FIN; k++) acc = fmaf(xr[k], sW[k * HH + col], acc);
        g_xw1[o] = acc;
    } else {
        int b = blockIdx.x - 128;
        int e0 = (b * 256 + threadIdx.x) * 4;
        if (e0 >= E) return;
        bool i64 = is_i64(ei);
        int d0, d1, d2, d3;
        if (e0 + 3 < E) {
            if (i64) {
                const longlong2* p = (const longlong2*)((const long long*)ei + E + e0);
                longlong2 v0 = __ldg(p), v1 = __ldg(p + 1);
                d0 = (int)v0.x; d1 = (int)v0.y; d2 = (int)v1.x; d3 = (int)v1.y;
            } else {
                int4 v = __ldg((const int4*)((const int*)ei + E + e0));
                d0 = v.x; d1 = v.y; d2 = v.z; d3 = v.w;
            }
            atomicAdd(&g_deg[d0], 1.0f);
            atomicAdd(&g_deg[d1], 1.0f);
            atomicAdd(&g_deg[d2], 1.0f);
            atomicAdd(&g_deg[d3], 1.0f);
        } else {
            for (int e = e0; e < E; e++)
                atomicAdd(&g_deg[edge_at(ei, i64, (long long)E + e)], 1.0f);
        }
    }
}

// dinv = rsqrt(deg + 1) (self-loop), then reset deg for the next replay.
__global__ void k_dinv() {
    int i = blockIdx.x * blockDim.x + threadIdx.x;
    if (i < NN) {
        g_dinv[i] = rsqrtf(g_deg[i] + 1.0f);
        g_deg[i] = 0.0f;
    }
}

// 4 threads per edge, 4 channels each: 1M scatter-adds with deep MLP.
__global__ void k_agg1(const void* __restrict__ ei, int E) {
    int gid = blockIdx.x * blockDim.x + threadIdx.x;
    int e = gid >> 2;
    if (e >= E) return;
    int c0 = (gid & 3) * 4;
    bool i64 = is_i64(ei);
    int s = edge_at(ei, i64, e);
    int d = edge_at(ei, i64, (long long)E + e);
    float nm = g_dinv[s] * g_dinv[d];
    float4 xs = *(const float4*)(g_xw1 + s * HH + c0);
    float* ad = g_agg1 + d * HH + c0;
    atomicAdd(ad + 0, xs.x * nm);
    atomicAdd(ad + 1, xs.y * nm);
    atomicAdd(ad + 2, xs.z * nm);
    atomicAdd(ad + 3, xs.w * nm);
}

// h = relu(agg1 + self + b1); xw2 = h@W2; A = h@Wc1[:16]; Bb = h@Wc1[16:] + bc1.
// Also resets agg1 for the next replay.
__global__ void k_h(const float* __restrict__ b1, const float* __restrict__ W2,
                    const float* __restrict__ Wc1, const float* __restrict__ bc1) {
    __shared__ float sWc1[32 * HH];
    __shared__ float sW2[HH * 2];
    int t = threadIdx.x;
    for (int idx = t; idx < 32 * HH; idx += blockDim.x) sWc1[idx] = Wc1[idx];
    if (t < HH * 2) sW2[t] = W2[t];
    __syncthreads();
    int i = blockIdx.x * blockDim.x + t;
    if (i >= NN) return;
    float di = g_dinv[i];
    float ds = di * di;
    float hv[HH];
#pragma unroll
    for (int c = 0; c < HH; c++) {
        float v = g_agg1[i * HH + c] + g_xw1[i * HH + c] * ds + b1[c];
        g_agg1[i * HH + c] = 0.0f;  // reset for next replay
        hv[c] = fmaxf(v, 0.0f);
    }
#pragma unroll
    for (int o = 0; o < 2; o++) {
        float a = 0.0f;
#pragma unroll
        for (int c = 0; c < HH; c++) a = fmaf(hv[c], sW2[c * 2 + o], a);
        g_xw2[i * 2 + o] = a;
    }
#pragma unroll
    for (int o = 0; o < HH; o++) {
        float a = 0.0f, b = bc1[o];
#pragma unroll
        for (int c = 0; c < HH; c++) {
            a = fmaf(hv[c], sWc1[c * HH + o], a);
            b = fmaf(hv[c], sWc1[(HH + c) * HH + o], b);
        }
        g_A[i * HH + o] = a;
        g_Bb[i * HH + o] = b;
    }
}

// 2 threads per edge for the 2-channel second aggregation.
__global__ void k_agg2(const void* __restrict__ ei, int E) {
    int gid = blockIdx.x * blockDim.x + threadIdx.x;
    int e = gid >> 1;
    if (e >= E) return;
    int c = gid & 1;
    bool i64 = is_i64(ei);
    int s = edge_at(ei, i64, e);
    int d = edge_at(ei, i64, (long long)E + e);
    float nm = g_dinv[s] * g_dinv[d];
    atomicAdd(&g_agg2[d * 2 + c], g_xw2[s * 2 + c] * nm);
}

// node_out; resets agg2 for the next replay.
__global__ void k_node(const float* __restrict__ b2, float* __restrict__ out) {
    int i = blockIdx.x * blockDim.x + threadIdx.x;
    if (i >= NN) return;
    float di = g_dinv[i];
    float ds = di * di;
    out[OFF_NODE + i * 2 + 0] = g_agg2[i * 2 + 0] + g_xw2[i * 2 + 0] * ds + b2[0];
    out[OFF_NODE + i * 2 + 1] = g_agg2[i * 2 + 1] + g_xw2[i * 2 + 1] * ds + b2[1];
    g_agg2[i * 2 + 0] = 0.0f;
    g_agg2[i * 2 + 1] = 0.0f;
}

// Fused edge MLP + index writes.
// edge_out[i*2048+j] = sigmoid( sum_c relu(A[i][c]+Bb[j][c]) * Wc2[c] + bc2 )
// start[i*2048+j] = i, end[i*2048+j] = j.
// Thread per j (coalesced stores), i-loop with A tile in smem read via LDS.128.
__global__ void __launch_bounds__(256) k_edge(const float* __restrict__ Wc2,
                                              const float* __restrict__ bc2,
                                              float* __restrict__ out) {
    __shared__ float sA[128 * HH];
    int t = threadIdx.x;
    int j = blockIdx.x * 256 + t;
    int i0 = blockIdx.y * 128;
    for (int idx = t; idx < 128 * HH; idx += 256) sA[idx] = g_A[i0 * HH + idx];
    float4 w[4];
#pragma unroll
    for (int q = 0; q < 4; q++) w[q] = *(const float4*)(Wc2 + q * 4);
    float bb = bc2[0];
    float4 B[4];
#pragma unroll
    for (int q = 0; q < 4; q++) B[q] = *(const float4*)(g_Bb + j * HH + q * 4);
    __syncthreads();
    float fj = (float)j;
    long long base = (long long)i0 * NN + j;
    float* oe = out + OFF_EDGE + base;
    float* os = out + OFF_START + base;
    float* od = out + OFF_END + base;
#pragma unroll 4
    for (int ii = 0; ii < 128; ii++) {
        const float4* a4 = (const float4*)(sA + ii * HH);
        float acc = bb;
#pragma unroll
        for (int q = 0; q < 4; q++) {
            float4 a = a4[q];
            acc = fmaf(fmaxf(a.x + B[q].x, 0.0f), w[q].x, acc);
            acc = fmaf(fmaxf(a.y + B[q].y, 0.0f), w[q].y, acc);
            acc = fmaf(fmaxf(a.z + B[q].z, 0.0f), w[q].z, acc);
            acc = fmaf(fmaxf(a.w + B[q].w, 0.0f), w[q].w, acc);
        }
        float p = __expf(-acc);
        int off = ii * NN;
        oe[off] = __fdividef(1.0f, 1.0f + p);
        os[off] = (float)(i0 + ii);
        od[off] = fj;
    }
}

// ---------------------------------------------------------------------------
extern "C" void kernel_launch(void* const* d_in, const int* in_sizes, int n_in,
                              void* d_out, int out_size) {
    const float* x   = (const float*)d_in[0];
    const void*  ei  = d_in[1];
    const float* W1  = (const float*)d_in[2];
    const float* b1  = (const float*)d_in[3];
    const float* W2  = (const float*)d_in[4];
    const float* b2  = (const float*)d_in[5];
    const float* Wc1 = (const float*)d_in[6];
    const float* bc1 = (const float*)d_in[7];
    const float* Wc2 = (const float*)d_in[8];
    const float* bc2 = (const float*)d_in[9];
    float* out = (float*)d_out;

    int E = in_sizes[1] / 2;

    int deg_blocks = (E + 1023) / 1024;
    k_pre<<<128 + deg_blocks, 256>>>(x, W1, ei, E);
    k_dinv<<<(NN + 255) / 256, 256>>>();
    k_agg1<<<(E * 4 + 255) / 256, 256>>>(ei, E);
    k_h<<<(NN + 255) / 256, 256>>>(b1, W2, Wc1, bc1);
    k_agg2<<<(E * 2 + 255) / 256, 256>>>(ei, E);
    k_node<<<(NN + 255) / 256, 256>>>(b2, out);
    dim3 eg(NN / 256, NN / 128);
    k_edge<<<eg, 256>>>(Wc2, bc2, out);
}

// round 5
// speedup vs baseline: 1.5632x; 1.2257x over previous
#include <cuda_runtime.h>
#include <cuda_bf16.h>

#define NN 2048
#define HH 16
#define FIN 128

// Output layout (float32): node_out [2048*2], edge_out [2048^2], start [2048^2], end [2048^2]
#define OFF_NODE  0
#define OFF_EDGE  4096
#define OFF_START (4096 + 4194304)
#define OFF_END   (4096 + 4194304 + 4194304)

// Scratch (static __device__ globals: zero-initialized at load; every kernel_launch
// call leaves them re-zeroed, so graph replays are deterministic).
__device__ float g_xw1[NN * HH];
__device__ float g_deg[NN];        // reset to 0 by k_dinv
__device__ float g_dinv[NN];
__device__ float g_agg1[NN * HH];  // reset to 0 by k_h
__device__ float g_xw2[NN * 2];
__device__ float g_agg2[NN * 2];   // reset to 0 by fused node block
__device__ float g_A[NN * HH];
__device__ float g_Bb[NN * HH];

// ---------------------------------------------------------------------------
// Inline dtype sniff: edge values < 2048, so for int64 the odd 32-bit words of
// the first 4 edges are all zero. Two uint4 loads, L1-broadcast, ~free.
__device__ __forceinline__ bool is_i64(const void* ei) {
    const uint4* p = (const uint4*)ei;
    uint4 a = __ldg(p), b = __ldg(p + 1);
    return ((a.y | a.w | b.y | b.w) == 0u);
}

__device__ __forceinline__ int edge_at(const void* ei, bool i64, long long idx) {
    if (i64) return (int)__ldg((const long long*)ei + idx);
    return __ldg((const int*)ei + idx);
}

// ---------------------------------------------------------------------------
// Fused: blocks [0,128) compute xw1 = x@W1; blocks [128, ...) count degrees.
__global__ void k_pre(const float* __restrict__ x, const float* __restrict__ W1,
                      const void* __restrict__ ei, int E) {
    if (blockIdx.x < 128) {
        __shared__ float sW[FIN * HH];
        int t = threadIdx.x;
        for (int idx = t; idx < FIN * HH; idx += 256) sW[idx] = W1[idx];
        __syncthreads();
        int o = blockIdx.x * 256 + t;
        int row = o >> 4, col = o & 15;
        const float* xr = x + row * FIN;
        float acc = 0.0f;
#pragma unroll 8
        for (int k = 0; k < FIN; k++) acc = fmaf(xr[k], sW[k * HH + col], acc);
        g_xw1[o] = acc;
    } else {
        int b = blockIdx.x - 128;
        int e0 = (b * 256 + threadIdx.x) * 4;
        if (e0 >= E) return;
        bool i64 = is_i64(ei);
        int d0, d1, d2, d3;
        if (e0 + 3 < E) {
            if (i64) {
                const longlong2* p = (const longlong2*)((const long long*)ei + E + e0);
                longlong2 v0 = __ldg(p), v1 = __ldg(p + 1);
                d0 = (int)v0.x; d1 = (int)v0.y; d2 = (int)v1.x; d3 = (int)v1.y;
            } else {
                int4 v = __ldg((const int4*)((const int*)ei + E + e0));
                d0 = v.x; d1 = v.y; d2 = v.z; d3 = v.w;
            }
            atomicAdd(&g_deg[d0], 1.0f);
            atomicAdd(&g_deg[d1], 1.0f);
            atomicAdd(&g_deg[d2], 1.0f);
            atomicAdd(&g_deg[d3], 1.0f);
        } else {
            for (int e = e0; e < E; e++)
                atomicAdd(&g_deg[edge_at(ei, i64, (long long)E + e)], 1.0f);
        }
    }
}

// dinv = rsqrt(deg + 1) (self-loop), reset deg for next replay.
__global__ void k_dinv() {
    int i = blockIdx.x * blockDim.x + threadIdx.x;
    if (i < NN) {
        g_dinv[i] = rsqrtf(g_deg[i] + 1.0f);
        g_deg[i] = 0.0f;
    }
}

// 4 threads per edge, 4 channels each: 1M scatter-adds with deep MLP.
__global__ void k_agg1(const void* __restrict__ ei, int E) {
    int gid = blockIdx.x * blockDim.x + threadIdx.x;
    int e = gid >> 2;
    if (e >= E) return;
    int c0 = (gid & 3) * 4;
    bool i64 = is_i64(ei);
    int s = edge_at(ei, i64, e);
    int d = edge_at(ei, i64, (long long)E + e);
    float nm = g_dinv[s] * g_dinv[d];
    float4 xs = *(const float4*)(g_xw1 + s * HH + c0);
    float* ad = g_agg1 + d * HH + c0;
    atomicAdd(ad + 0, xs.x * nm);
    atomicAdd(ad + 1, xs.y * nm);
    atomicAdd(ad + 2, xs.z * nm);
    atomicAdd(ad + 3, xs.w * nm);
}

// Warp-per-node: lanes 0-15 compute hv[c], shfl-broadcast through the dot;
// lanes 0-15 emit A[o], lanes 16-31 emit Bb[o], lanes 0-1 emit xw2.
// Resets agg1 for the next replay.
__global__ void __launch_bounds__(256) k_h(const float* __restrict__ b1,
                                           const float* __restrict__ W2,
                                           const float* __restrict__ Wc1,
                                           const float* __restrict__ bc1) {
    __shared__ float sWc1[32 * HH];
    int t = threadIdx.x;
    for (int idx = t; idx < 32 * HH; idx += 256) sWc1[idx] = Wc1[idx];
    __syncthreads();
    int warp = t >> 5, lane = t & 31;
    int i = blockIdx.x * 8 + warp;
    float di = g_dinv[i];
    float ds = di * di;
    float myhv = 0.0f;
    if (lane < HH) {
        float v = g_agg1[i * HH + lane] + g_xw1[i * HH + lane] * ds + __ldg(b1 + lane);
        g_agg1[i * HH + lane] = 0.0f;
        myhv = fmaxf(v, 0.0f);
    }
    int o = lane & 15;
    int half = lane >> 4;  // 0 -> A, 1 -> Bb
    float wreg[HH];
#pragma unroll
    for (int c = 0; c < HH; c++) wreg[c] = sWc1[(half * HH + c) * HH + o];
    float w2reg[HH];
    if (lane < 2) {
#pragma unroll
        for (int c = 0; c < HH; c++) w2reg[c] = __ldg(W2 + c * 2 + lane);
    }
    float acc = half ? __ldg(bc1 + o) : 0.0f;
    float acc2 = 0.0f;
#pragma unroll
    for (int c = 0; c < HH; c++) {
        float hc = __shfl_sync(0xffffffffu, myhv, c);
        acc = fmaf(hc, wreg[c], acc);
        if (lane < 2) acc2 = fmaf(hc, w2reg[c], acc2);
    }
    if (half == 0) g_A[i * HH + o] = acc;
    else           g_Bb[i * HH + o] = acc;
    if (lane < 2)  g_xw2[i * 2 + lane] = acc2;
}

// 2 threads per edge for the 2-channel second aggregation.
__global__ void k_agg2(const void* __restrict__ ei, int E) {
    int gid = blockIdx.x * blockDim.x + threadIdx.x;
    int e = gid >> 1;
    if (e >= E) return;
    int c = gid & 1;
    bool i64 = is_i64(ei);
    int s = edge_at(ei, i64, e);
    int d = edge_at(ei, i64, (long long)E + e);
    float nm = g_dinv[s] * g_dinv[d];
    atomicAdd(&g_agg2[d * 2 + c], g_xw2[s * 2 + c] * nm);
}

// Fused: edge MLP + index writes (blockIdx.x < 8), node_out (blockIdx.x == 8).
__global__ void __launch_bounds__(256) k_edge(const float* __restrict__ Wc2,
                                              const float* __restrict__ bc2,
                                              const float* __restrict__ b2,
                                              float* __restrict__ out) {
    int t = threadIdx.x;
    if (blockIdx.x == 8) {
        // node_out: 16 y-blocks x 256 threads = 4096 = 2048 nodes x 2 ch
        int i = blockIdx.y * 128 + (t >> 1);
        int c = t & 1;
        float di = g_dinv[i];
        float ds = di * di;
        out[OFF_NODE + i * 2 + c] = g_agg2[i * 2 + c] + g_xw2[i * 2 + c] * ds + __ldg(b2 + c);
        g_agg2[i * 2 + c] = 0.0f;  // reset for next replay
        return;
    }
    __shared__ float sA[128 * HH];
    int j = blockIdx.x * 256 + t;
    int i0 = blockIdx.y * 128;
    for (int idx = t; idx < 128 * HH; idx += 256) sA[idx] = g_A[i0 * HH + idx];
    float4 w[4];
#pragma unroll
    for (int q = 0; q < 4; q++) w[q] = *(const float4*)(Wc2 + q * 4);
    float bb = bc2[0];
    float4 B[4];
#pragma unroll
    for (int q = 0; q < 4; q++) B[q] = *(const float4*)(g_Bb + j * HH + q * 4);
    __syncthreads();
    float fj = (float)j;
    long long base = (long long)i0 * NN + j;
    float* oe = out + OFF_EDGE + base;
    float* os = out + OFF_START + base;
    float* od = out + OFF_END + base;
#pragma unroll 4
    for (int ii = 0; ii < 128; ii++) {
        const float4* a4 = (const float4*)(sA + ii * HH);
        float acc = bb;
#pragma unroll
        for (int q = 0; q < 4; q++) {
            float4 a = a4[q];
            acc = fmaf(fmaxf(a.x + B[q].x, 0.0f), w[q].x, acc);
            acc = fmaf(fmaxf(a.y + B[q].y, 0.0f), w[q].y, acc);
            acc = fmaf(fmaxf(a.z + B[q].z, 0.0f), w[q].z, acc);
            acc = fmaf(fmaxf(a.w + B[q].w, 0.0f), w[q].w, acc);
        }
        float p = __expf(-acc);
        int off = ii * NN;
        oe[off] = __fdividef(1.0f, 1.0f + p);
        os[off] = (float)(i0 + ii);
        od[off] = fj;
    }
}

// ---------------------------------------------------------------------------
extern "C" void kernel_launch(void* const* d_in, const int* in_sizes, int n_in,
                              void* d_out, int out_size) {
    const float* x   = (const float*)d_in[0];
    const void*  ei  = d_in[1];
    const float* W1  = (const float*)d_in[2];
    const float* b1  = (const float*)d_in[3];
    const float* W2  = (const float*)d_in[4];
    const float* b2  = (const float*)d_in[5];
    const float* Wc1 = (const float*)d_in[6];
    const float* bc1 = (const float*)d_in[7];
    const float* Wc2 = (const float*)d_in[8];
    const float* bc2 = (const float*)d_in[9];
    float* out = (float*)d_out;

    int E = in_sizes[1] / 2;

    int deg_blocks = (E + 1023) / 1024;
    k_pre<<<128 + deg_blocks, 256>>>(x, W1, ei, E);
    k_dinv<<<(NN + 255) / 256, 256>>>();
    k_agg1<<<(E * 4 + 255) / 256, 256>>>(ei, E);
    k_h<<<NN / 8, 256>>>(b1, W2, Wc1, bc1);
    k_agg2<<<(E * 2 + 255) / 256, 256>>>(ei, E);
    dim3 eg(9, NN / 128);
    k_edge<<<eg, 256>>>(Wc2, bc2, b2, out);
}